// round 1
// baseline (speedup 1.0000x reference)
#include <cuda_runtime.h>
#include <math.h>

// Problem dims (fixed by the reference)
#define Bsz 4096
#define Hd  2048
#define Kd  2048   // all reduction dims are 2048 (D == H)

// Scratch (device globals: allocation-free per harness rules)
__device__ float g_Z[(size_t)Bsz * (5 * Hd)];   // [B, 5H]: i | f | g | o_partial | residual
__device__ float g_Z2[(size_t)Bsz * (2 * Hd)];  // [B, 2H]: c@w_co | tanh(c)@w_c
__device__ float g_tanhc[(size_t)Bsz * Hd];     // tanh(c_new)

#define BM 128
#define BN 128
#define BK 16

// Accumulate acc += A[m0:m0+128, :Kd] @ W[:, j0:j0+128]  (A row-major lda=Kd, W row-major ldw=Hd)
__device__ __forceinline__ void gemm_accum(
    const float* __restrict__ A, const float* __restrict__ W,
    int m0, int j0, float acc[8][8],
    float (*As)[BM], float (*Ws)[BN])
{
    const int tid   = threadIdx.x;
    const int a_row = tid >> 2;          // 0..63
    const int a_col = (tid & 3) << 2;    // 0,4,8,12
    const int w_row = tid >> 5;          // 0..7
    const int w_col = (tid & 31) << 2;   // 0..124
    const int tx    = tid & 15;
    const int ty    = tid >> 4;

    const float* Ap = A + (size_t)(m0 + a_row) * Kd + a_col;
    const float* Wp = W + (size_t)w_row * Hd + j0 + w_col;

    // prefetch tile 0
    float4 a0 = *(const float4*)(Ap);
    float4 a1 = *(const float4*)(Ap + (size_t)64 * Kd);
    float4 w0 = *(const float4*)(Wp);
    float4 w1 = *(const float4*)(Wp + (size_t)8 * Hd);

    for (int kt = 0; kt < Kd; kt += BK) {
        // regs -> smem (A stored transposed for conflict-free column reads)
        As[a_col + 0][a_row]      = a0.x;
        As[a_col + 1][a_row]      = a0.y;
        As[a_col + 2][a_row]      = a0.z;
        As[a_col + 3][a_row]      = a0.w;
        As[a_col + 0][a_row + 64] = a1.x;
        As[a_col + 1][a_row + 64] = a1.y;
        As[a_col + 2][a_row + 64] = a1.z;
        As[a_col + 3][a_row + 64] = a1.w;
        *(float4*)(&Ws[w_row][w_col])     = w0;
        *(float4*)(&Ws[w_row + 8][w_col]) = w1;
        __syncthreads();

        // prefetch next tile while computing this one
        if (kt + BK < Kd) {
            a0 = *(const float4*)(Ap + kt + BK);
            a1 = *(const float4*)(Ap + (size_t)64 * Kd + kt + BK);
            w0 = *(const float4*)(Wp + (size_t)(kt + BK) * Hd);
            w1 = *(const float4*)(Wp + (size_t)(kt + BK + 8) * Hd);
        }

        #pragma unroll
        for (int k = 0; k < BK; ++k) {
            float af[8], wf[8];
            #pragma unroll
            for (int i = 0; i < 8; ++i) af[i] = As[k][ty * 8 + i];
            #pragma unroll
            for (int j = 0; j < 8; ++j) wf[j] = Ws[k][tx * 8 + j];
            #pragma unroll
            for (int i = 0; i < 8; ++i)
                #pragma unroll
                for (int j = 0; j < 8; ++j)
                    acc[i][j] = fmaf(af[i], wf[j], acc[i][j]);
        }
        __syncthreads();
    }
}

// GEMM1: Z[B, 5H]. Column group g = blockIdx.x/16 selects which phase list to run.
//   g=0 (i): x@w_xi + h@w_hi + c@w_ci + b_i
//   g=1 (f): x@w_xf + h@w_hf + c@w_cf + b_f
//   g=2 (g): x@w_xg + h@w_hg + b_g
//   g=3 (o): x@w_xo + h@w_ho + b_o
//   g=4 (r): x@w_i
__global__ void __launch_bounds__(256) gemm1_kernel(
    const float* __restrict__ x, const float* __restrict__ h, const float* __restrict__ c,
    const float* __restrict__ w_xi, const float* __restrict__ w_hi, const float* __restrict__ w_ci,
    const float* __restrict__ w_xf, const float* __restrict__ w_hf, const float* __restrict__ w_cf,
    const float* __restrict__ w_xg, const float* __restrict__ w_hg,
    const float* __restrict__ w_xo, const float* __restrict__ w_ho,
    const float* __restrict__ w_i,
    const float* __restrict__ b_i, const float* __restrict__ b_f,
    const float* __restrict__ b_g, const float* __restrict__ b_o)
{
    __shared__ float As[BK][BM];
    __shared__ float Ws[BK][BN];

    const int g  = blockIdx.x >> 4;           // 2048/128 = 16 col-blocks per group
    const int j0 = (blockIdx.x & 15) * BN;    // col offset within the group's weight
    const int m0 = blockIdx.y * BM;

    const float* Ap[3]; const float* Wp[3]; int nph;
    const float* bias;
    switch (g) {
        case 0: Ap[0]=x; Wp[0]=w_xi; Ap[1]=h; Wp[1]=w_hi; Ap[2]=c; Wp[2]=w_ci; nph=3; bias=b_i; break;
        case 1: Ap[0]=x; Wp[0]=w_xf; Ap[1]=h; Wp[1]=w_hf; Ap[2]=c; Wp[2]=w_cf; nph=3; bias=b_f; break;
        case 2: Ap[0]=x; Wp[0]=w_xg; Ap[1]=h; Wp[1]=w_hg;                      nph=2; bias=b_g; break;
        case 3: Ap[0]=x; Wp[0]=w_xo; Ap[1]=h; Wp[1]=w_ho;                      nph=2; bias=b_o; break;
        default:Ap[0]=x; Wp[0]=w_i;                                            nph=1; bias=nullptr; break;
    }

    float acc[8][8];
    #pragma unroll
    for (int i = 0; i < 8; ++i)
        #pragma unroll
        for (int j = 0; j < 8; ++j) acc[i][j] = 0.0f;

    for (int ph = 0; ph < nph; ++ph)
        gemm_accum(Ap[ph], Wp[ph], m0, j0, acc, As, Ws);

    const int tx = threadIdx.x & 15;
    const int ty = threadIdx.x >> 4;

    float4 b0 = make_float4(0.f, 0.f, 0.f, 0.f);
    float4 b1 = b0;
    if (bias) {
        b0 = *(const float4*)(bias + j0 + tx * 8);
        b1 = *(const float4*)(bias + j0 + tx * 8 + 4);
    }

    const size_t ldz = 5 * Hd;
    float* Zr = g_Z + (size_t)(m0 + ty * 8) * ldz + (size_t)g * Hd + j0 + tx * 8;
    #pragma unroll
    for (int i = 0; i < 8; ++i) {
        float4 v0 = make_float4(acc[i][0] + b0.x, acc[i][1] + b0.y,
                                acc[i][2] + b0.z, acc[i][3] + b0.w);
        float4 v1 = make_float4(acc[i][4] + b1.x, acc[i][5] + b1.y,
                                acc[i][6] + b1.z, acc[i][7] + b1.w);
        *(float4*)(Zr + (size_t)i * ldz)     = v0;
        *(float4*)(Zr + (size_t)i * ldz + 4) = v1;
    }
}

// Elementwise cell update: c_new = sigmoid(f)*c_prev + sigmoid(i)*tanh(g)
__global__ void __launch_bounds__(256) cell_kernel(
    const float* __restrict__ c_prev, float* __restrict__ c_out)
{
    const int idx = blockIdx.x * 256 + threadIdx.x;   // over B*H (exact multiple)
    const int m = idx >> 11;
    const int j = idx & (Hd - 1);
    const float* zr = g_Z + (size_t)m * (5 * Hd);
    const float iv = zr[j];
    const float fv = zr[Hd + j];
    const float gv = zr[2 * Hd + j];
    const float cp = c_prev[idx];
    const float si = 1.0f / (1.0f + expf(-iv));
    const float sf = 1.0f / (1.0f + expf(-fv));
    const float cn = sf * cp + si * tanhf(gv);
    c_out[idx]    = cn;
    g_tanhc[idx]  = tanhf(cn);
}

// GEMM2: Z2[B, 2H] = [ c_new @ w_co | tanh(c_new) @ w_c ]
__global__ void __launch_bounds__(256) gemm2_kernel(
    const float* __restrict__ c_new,
    const float* __restrict__ w_co, const float* __restrict__ w_c)
{
    __shared__ float As[BK][BM];
    __shared__ float Ws[BK][BN];

    const int g  = blockIdx.x >> 4;           // 0 or 1
    const int j0 = (blockIdx.x & 15) * BN;
    const int m0 = blockIdx.y * BM;

    const float* A = (g == 0) ? c_new : (const float*)g_tanhc;
    const float* W = (g == 0) ? w_co  : w_c;

    float acc[8][8];
    #pragma unroll
    for (int i = 0; i < 8; ++i)
        #pragma unroll
        for (int j = 0; j < 8; ++j) acc[i][j] = 0.0f;

    gemm_accum(A, W, m0, j0, acc, As, Ws);

    const int tx = threadIdx.x & 15;
    const int ty = threadIdx.x >> 4;
    const size_t ldz = 2 * Hd;
    float* Zr = g_Z2 + (size_t)(m0 + ty * 8) * ldz + (size_t)g * Hd + j0 + tx * 8;
    #pragma unroll
    for (int i = 0; i < 8; ++i) {
        float4 v0 = make_float4(acc[i][0], acc[i][1], acc[i][2], acc[i][3]);
        float4 v1 = make_float4(acc[i][4], acc[i][5], acc[i][6], acc[i][7]);
        *(float4*)(Zr + (size_t)i * ldz)     = v0;
        *(float4*)(Zr + (size_t)i * ldz + 4) = v1;
    }
}

// Final elementwise: o = o_partial + c@w_co (bias already in o_partial);
// h = tanh(o) * (tanh(c)@w_c + residual)
__global__ void __launch_bounds__(256) out_kernel(float* __restrict__ h_out)
{
    const int idx = blockIdx.x * 256 + threadIdx.x;
    const int m = idx >> 11;
    const int j = idx & (Hd - 1);
    const float* zr  = g_Z  + (size_t)m * (5 * Hd);
    const float* z2r = g_Z2 + (size_t)m * (2 * Hd);
    const float o = zr[3 * Hd + j] + z2r[j];
    const float t = z2r[Hd + j] + zr[4 * Hd + j];
    h_out[idx] = tanhf(o) * t;
}

extern "C" void kernel_launch(void* const* d_in, const int* in_sizes, int n_in,
                              void* d_out, int out_size)
{
    // metadata order: input_, h_prev, c_prev, w_xi, w_hi, w_ci, w_xf, w_hf, w_cf,
    //                 w_xg, w_hg, w_xo, w_ho, w_co, w_c, w_i, b_i, b_f, b_g, b_o
    const float* x      = (const float*)d_in[0];
    const float* h_prev = (const float*)d_in[1];
    const float* c_prev = (const float*)d_in[2];
    const float* w_xi   = (const float*)d_in[3];
    const float* w_hi   = (const float*)d_in[4];
    const float* w_ci   = (const float*)d_in[5];
    const float* w_xf   = (const float*)d_in[6];
    const float* w_hf   = (const float*)d_in[7];
    const float* w_cf   = (const float*)d_in[8];
    const float* w_xg   = (const float*)d_in[9];
    const float* w_hg   = (const float*)d_in[10];
    const float* w_xo   = (const float*)d_in[11];
    const float* w_ho   = (const float*)d_in[12];
    const float* w_co   = (const float*)d_in[13];
    const float* w_c    = (const float*)d_in[14];
    const float* w_i    = (const float*)d_in[15];
    const float* b_i    = (const float*)d_in[16];
    const float* b_f    = (const float*)d_in[17];
    const float* b_g    = (const float*)d_in[18];
    const float* b_o    = (const float*)d_in[19];

    float* out   = (float*)d_out;
    float* h_out = out;                              // h: first B*H
    float* c_out = out + (size_t)Bsz * Hd;           // c: second B*H

    const int n = Bsz * Hd;                          // 8388608, multiple of 256

    gemm1_kernel<<<dim3(5 * (Hd / BN), Bsz / BM), 256>>>(
        x, h_prev, c_prev,
        w_xi, w_hi, w_ci,
        w_xf, w_hf, w_cf,
        w_xg, w_hg,
        w_xo, w_ho,
        w_i,
        b_i, b_f, b_g, b_o);

    cell_kernel<<<n / 256, 256>>>(c_prev, c_out);

    gemm2_kernel<<<dim3(2 * (Hd / BN), Bsz / BM), 256>>>(c_out, w_co, w_c);

    out_kernel<<<n / 256, 256>>>(h_out);
}

// round 3
// speedup vs baseline: 2.1438x; 2.1438x over previous
#include <cuda_runtime.h>
#include <cuda_bf16.h>
#include <math.h>
#include <stdint.h>

// ---------------- problem dims ----------------
#define Bsz 4096
#define Hd  2048
#define Kd  2048
#define AP  (4096ull*2048ull)   // activation plane elems
#define WP  (2048ull*2048ull)   // weight plane elems

// ---------------- device scratch ----------------
__device__ float g_Z [(size_t)Bsz*(5*Hd)];  // [B,5H]: i|f|g|o_part|resid
__device__ float g_Z2[(size_t)Bsz*(2*Hd)];  // [B,2H]: c@w_co | tanh(c)@w_c
// bf16 activations [plane][B][K]; planes: 0=x_hi 1=x_lo 2=h_hi 3=h_lo 4=c_hi 5=c_lo
//                                          6=cnew_hi 7=cnew_lo 8=tanhc_hi 9=tanhc_lo
__device__ __nv_bfloat16 g_Act[10ull*AP];
// bf16 weights transposed [plane][N][K]; plane z = 2*widx + split
// widx: 0 wxi 1 whi 2 wci 3 wxf 4 whf 5 wcf 6 wxg 7 whg 8 wxo 9 who 10 wco 11 wc 12 wi
__device__ __nv_bfloat16 g_Wt[26ull*WP];

// ---------------- segment tables ----------------
// groups: 0=i 1=f 2=g 3=o 4=resid 5=co 6=c
// each (activation, weight) unit -> 3 passes: (a_hi,w_hi),(a_hi,w_lo),(a_lo,w_hi)
__constant__ int c_nseg[7] = {9, 9, 6, 6, 3, 3, 3};
__constant__ unsigned char c_seg_a[7][9] = {
    {0,0,1, 2,2,3, 4,4,5},   // i : x*wxi + h*whi + c*wci
    {0,0,1, 2,2,3, 4,4,5},   // f : x*wxf + h*whf + c*wcf
    {0,0,1, 2,2,3, 0,0,0},   // g : x*wxg + h*whg
    {0,0,1, 2,2,3, 0,0,0},   // o : x*wxo + h*who
    {0,0,1, 0,0,0, 0,0,0},   // r : x*wi
    {6,6,7, 0,0,0, 0,0,0},   // co: c_new*w_co
    {8,8,9, 0,0,0, 0,0,0},   // c : tanh(c_new)*w_c
};
__constant__ unsigned char c_seg_w[7][9] = {
    {0,1,0,  2,3,2,  4,5,4},      // wxi whi wci
    {6,7,6,  8,9,8,  10,11,10},   // wxf whf wcf
    {12,13,12, 14,15,14, 0,0,0},  // wxg whg
    {16,17,16, 18,19,18, 0,0,0},  // wxo who
    {24,25,24, 0,0,0, 0,0,0},     // wi
    {20,21,20, 0,0,0, 0,0,0},     // wco
    {22,23,22, 0,0,0, 0,0,0},     // wc
};

// ---------------- GEMM tiling ----------------
#define BM 128
#define BN 256
#define BKc 32
#define KPAD 40                    // 32 + 8 pad (16B) for conflict-free ldmatrix
#define STAGES 4
#define THREADS 256
#define A_ST (BM*KPAD)             // 5120 elems
#define B_ST (BN*KPAD)             // 10240 elems
#define ST_ELEMS (A_ST + B_ST)     // 15360 elems = 30720 B
#define SMEM_BYTES (STAGES*ST_ELEMS*2)

__device__ __forceinline__ uint32_t smem_u32(const void* p) {
    uint32_t a;
    asm("{ .reg .u64 t; cvta.to.shared.u64 t, %1; cvt.u32.u64 %0, t; }" : "=r"(a) : "l"(p));
    return a;
}

__device__ __forceinline__ void cp_async16(uint32_t sdst, const void* gsrc) {
    asm volatile("cp.async.cg.shared.global [%0], [%1], 16;"
                 :: "r"(sdst), "l"(__cvta_generic_to_global(gsrc)) : "memory");
}
#define CP_COMMIT() asm volatile("cp.async.commit_group;" ::: "memory")
#define CP_WAIT2()  asm volatile("cp.async.wait_group 2;" ::: "memory")

__device__ __forceinline__ void ldsm_x4(uint32_t& r0, uint32_t& r1, uint32_t& r2, uint32_t& r3,
                                        uint32_t addr) {
    asm volatile("ldmatrix.sync.aligned.m8n8.x4.shared.b16 {%0,%1,%2,%3}, [%4];"
                 : "=r"(r0), "=r"(r1), "=r"(r2), "=r"(r3) : "r"(addr));
}

__device__ __forceinline__ void mma16816(float* d, const uint32_t* a, const uint32_t* b) {
    asm volatile(
        "mma.sync.aligned.m16n8k16.row.col.f32.bf16.bf16.f32 "
        "{%0,%1,%2,%3}, {%4,%5,%6,%7}, {%8,%9}, {%0,%1,%2,%3};"
        : "+f"(d[0]), "+f"(d[1]), "+f"(d[2]), "+f"(d[3])
        : "r"(a[0]), "r"(a[1]), "r"(a[2]), "r"(a[3]), "r"(b[0]), "r"(b[1]));
}

// ---------------- fused split-bf16 GEMM (HMMA path) ----------------
__global__ void __launch_bounds__(THREADS, 1) gemm_mma(
    int group_base,
    const float* __restrict__ bi, const float* __restrict__ bf_,
    const float* __restrict__ bg, const float* __restrict__ bo)
{
    extern __shared__ __nv_bfloat16 smem[];
    const uint32_t sb = smem_u32(smem);

    const int tid  = threadIdx.x;
    const int lane = tid & 31;
    const int wid  = tid >> 5;
    const int wm   = wid >> 2;     // 0..1
    const int wn   = wid & 3;      // 0..3

    const int group = group_base + ((int)blockIdx.y >> 3);
    const int n0    = ((int)blockIdx.y & 7) * BN;
    const int m0    = (int)blockIdx.x * BM;

    const int nseg = c_nseg[group];
    const int nch  = nseg * (Kd / BKc);   // k32 chunks

    // per-thread cp.async coordinates (6 chunks of 16B per thread per stage)
    // chunk id cid in [0,1536): [0,512) -> A, [512,1536) -> B
    // A: row = cid>>2 (0..127), colc = cid&3 ; B: row = (cid-512)>>2 (0..255)
    // ldmatrix lane offsets (bytes)
    const uint32_t a_off = ((uint32_t)(wm*64 + (lane & 15)) * KPAD + ((lane >> 4) << 3)) * 2;
    const uint32_t b_off = ((uint32_t)(wn*64 + (lane & 7) + ((lane >> 4) << 3)) * KPAD
                            + (((lane >> 3) & 1) << 3)) * 2;

    float acc[4][8][4];
    #pragma unroll
    for (int mi = 0; mi < 4; ++mi)
        #pragma unroll
        for (int nj = 0; nj < 8; ++nj)
            #pragma unroll
            for (int r = 0; r < 4; ++r) acc[mi][nj][r] = 0.0f;

    // ---- issue helper (as lambda-ish macro) ----
    #define ISSUE(tt, buf) do {                                                        \
        const int _t = (tt);                                                           \
        const int _seg = _t >> 6;                                                      \
        const int _kk  = (_t & 63) * BKc;                                              \
        const __nv_bfloat16* _gA = g_Act + (size_t)c_seg_a[group][_seg]*AP;            \
        const __nv_bfloat16* _gW = g_Wt  + (size_t)c_seg_w[group][_seg]*WP;            \
        const uint32_t _sbase = sb + (uint32_t)(buf)*ST_ELEMS*2;                       \
        _Pragma("unroll")                                                              \
        for (int _i = 0; _i < 6; ++_i) {                                               \
            const int _cid = tid + _i*THREADS;                                         \
            if (_cid < 512) {                                                          \
                const int _r = _cid >> 2, _cc = _cid & 3;                              \
                cp_async16(_sbase + (uint32_t)(_r*KPAD + _cc*8)*2,                     \
                           _gA + (size_t)(m0 + _r)*Kd + _kk + _cc*8);                  \
            } else {                                                                   \
                const int _b = _cid - 512;                                             \
                const int _r = _b >> 2, _cc = _b & 3;                                  \
                cp_async16(_sbase + (uint32_t)(A_ST + _r*KPAD + _cc*8)*2,              \
                           _gW + (size_t)(n0 + _r)*Kd + _kk + _cc*8);                  \
            }                                                                          \
        }                                                                              \
    } while (0)

    // prologue: stages 0..STAGES-2
    #pragma unroll
    for (int s = 0; s < STAGES-1; ++s) {
        ISSUE(s, s);
        CP_COMMIT();
    }

    for (int t = 0; t < nch; ++t) {
        CP_WAIT2();
        __syncthreads();

        // prefetch stage t+3 into buffer (t+3)%4 == (t-1)%4 (free since last iter)
        if (t + STAGES - 1 < nch) ISSUE(t + STAGES - 1, (t + STAGES - 1) & 3);
        CP_COMMIT();   // always commit (possibly empty group) to keep counts aligned

        const uint32_t st = sb + (uint32_t)(t & 3)*ST_ELEMS*2;

        #pragma unroll
        for (int ks = 0; ks < 2; ++ks) {
            uint32_t af[4][4];
            uint32_t bfr[4][4];
            #pragma unroll
            for (int mi = 0; mi < 4; ++mi)
                ldsm_x4(af[mi][0], af[mi][1], af[mi][2], af[mi][3],
                        st + a_off + (uint32_t)(mi*16*KPAD + ks*16)*2);
            #pragma unroll
            for (int nt = 0; nt < 4; ++nt)
                ldsm_x4(bfr[nt][0], bfr[nt][1], bfr[nt][2], bfr[nt][3],
                        st + (uint32_t)A_ST*2 + b_off + (uint32_t)(nt*16*KPAD + ks*16)*2);

            #pragma unroll
            for (int mi = 0; mi < 4; ++mi)
                #pragma unroll
                for (int nj = 0; nj < 8; ++nj) {
                    uint32_t bb[2];
                    bb[0] = bfr[nj >> 1][(nj & 1) * 2 + 0];
                    bb[1] = bfr[nj >> 1][(nj & 1) * 2 + 1];
                    mma16816(acc[mi][nj], af[mi], bb);
                }
        }
    }

    // ---- epilogue ----
    float* zout; size_t ldz; int colbase;
    const float* bias = nullptr;
    if (group < 5) {
        zout = g_Z;  ldz = 5*Hd; colbase = group*Hd + n0;
        if      (group == 0) bias = bi;
        else if (group == 1) bias = bf_;
        else if (group == 2) bias = bg;
        else if (group == 3) bias = bo;
    } else {
        zout = g_Z2; ldz = 2*Hd; colbase = (group - 5)*Hd + n0;
    }

    const int gid = lane >> 2;
    const int tig = lane & 3;

    #pragma unroll
    for (int mi = 0; mi < 4; ++mi) {
        const int row = m0 + wm*64 + mi*16 + gid;
        #pragma unroll
        for (int nj = 0; nj < 8; ++nj) {
            const int ncol = wn*64 + nj*8 + tig*2;     // within group's 2048... (n0 added below)
            float b0 = 0.f, b1 = 0.f;
            if (bias) { b0 = bias[n0 + ncol]; b1 = bias[n0 + ncol + 1]; }
            float2 v0 = make_float2(acc[mi][nj][0] + b0, acc[mi][nj][1] + b1);
            float2 v1 = make_float2(acc[mi][nj][2] + b0, acc[mi][nj][3] + b1);
            *(float2*)(zout + (size_t)row      * ldz + colbase + ncol) = v0;
            *(float2*)(zout + (size_t)(row + 8)* ldz + colbase + ncol) = v1;
        }
    }
}

// ---------------- conversion kernels ----------------
__device__ __forceinline__ void split_store(__nv_bfloat16* hi, __nv_bfloat16* lo,
                                            size_t idx, float v) {
    __nv_bfloat16 h = __float2bfloat16_rn(v);
    hi[idx] = h;
    lo[idx] = __float2bfloat16_rn(v - __bfloat162float(h));
}

// x/h/c fp32 -> bf16 hi/lo planes 0..5
__global__ void __launch_bounds__(256) conv_act3(
    const float* __restrict__ x, const float* __restrict__ h, const float* __restrict__ c)
{
    const int act = blockIdx.y;
    const float* s = (act == 0) ? x : (act == 1) ? h : c;
    const size_t i = ((size_t)blockIdx.x*256 + threadIdx.x) * 4;
    float4 v = *(const float4*)(s + i);
    __nv_bfloat16* hi = g_Act + (size_t)(2*act)*AP;
    __nv_bfloat16* lo = hi + AP;
    split_store(hi, lo, i+0, v.x);
    split_store(hi, lo, i+1, v.y);
    split_store(hi, lo, i+2, v.z);
    split_store(hi, lo, i+3, v.w);
}

struct WPtrs { const float* p[13]; };

// W[K][N] fp32 -> g_Wt[N][K] bf16 hi/lo (transpose via smem tile)
__global__ void __launch_bounds__(256) conv_w(WPtrs wp)
{
    __shared__ float t[32][33];
    const int widx = blockIdx.z;
    const float* w = wp.p[widx];
    const int tx = threadIdx.x & 31;
    const int ty = threadIdx.x >> 5;        // 0..7
    const int k0 = blockIdx.x * 32;
    const int n0 = blockIdx.y * 32;
    #pragma unroll
    for (int r = 0; r < 4; ++r)
        t[ty + 8*r][tx] = w[(size_t)(k0 + ty + 8*r)*Hd + n0 + tx];
    __syncthreads();
    __nv_bfloat16* hi = g_Wt + (size_t)(2*widx)*WP;
    __nv_bfloat16* lo = hi + WP;
    #pragma unroll
    for (int r = 0; r < 4; ++r) {
        const float v = t[tx][ty + 8*r];
        const size_t o = (size_t)(n0 + ty + 8*r)*Kd + k0 + tx;
        __nv_bfloat16 hb = __float2bfloat16_rn(v);
        hi[o] = hb;
        lo[o] = __float2bfloat16_rn(v - __bfloat162float(hb));
    }
}

// ---------------- elementwise kernels ----------------
__global__ void __launch_bounds__(256) cell_kernel(
    const float* __restrict__ c_prev, float* __restrict__ c_out)
{
    const int idx = blockIdx.x * 256 + threadIdx.x;
    const int m = idx >> 11;
    const int j = idx & (Hd - 1);
    const float* zr = g_Z + (size_t)m * (5*Hd);
    const float iv = zr[j];
    const float fv = zr[Hd + j];
    const float gv = zr[2*Hd + j];
    const float cp = c_prev[idx];
    const float si = 1.0f / (1.0f + expf(-iv));
    const float sf = 1.0f / (1.0f + expf(-fv));
    const float cn = sf * cp + si * tanhf(gv);
    c_out[idx] = cn;
    const float tc = tanhf(cn);
    split_store(g_Act + 6*AP, g_Act + 7*AP, idx, cn);
    split_store(g_Act + 8*AP, g_Act + 9*AP, idx, tc);
}

__global__ void __launch_bounds__(256) out_kernel(float* __restrict__ h_out)
{
    const int idx = blockIdx.x * 256 + threadIdx.x;
    const int m = idx >> 11;
    const int j = idx & (Hd - 1);
    const float* zr  = g_Z  + (size_t)m * (5*Hd);
    const float* z2r = g_Z2 + (size_t)m * (2*Hd);
    const float o = zr[3*Hd + j] + z2r[j];
    const float t = z2r[Hd + j] + zr[4*Hd + j];
    h_out[idx] = tanhf(o) * t;
}

// ---------------- host launcher ----------------
extern "C" void kernel_launch(void* const* d_in, const int* in_sizes, int n_in,
                              void* d_out, int out_size)
{
    const float* x      = (const float*)d_in[0];
    const float* h_prev = (const float*)d_in[1];
    const float* c_prev = (const float*)d_in[2];
    const float* w_xi = (const float*)d_in[3];
    const float* w_hi = (const float*)d_in[4];
    const float* w_ci = (const float*)d_in[5];
    const float* w_xf = (const float*)d_in[6];
    const float* w_hf = (const float*)d_in[7];
    const float* w_cf = (const float*)d_in[8];
    const float* w_xg = (const float*)d_in[9];
    const float* w_hg = (const float*)d_in[10];
    const float* w_xo = (const float*)d_in[11];
    const float* w_ho = (const float*)d_in[12];
    const float* w_co = (const float*)d_in[13];
    const float* w_c  = (const float*)d_in[14];
    const float* w_i  = (const float*)d_in[15];
    const float* b_i  = (const float*)d_in[16];
    const float* b_f  = (const float*)d_in[17];
    const float* b_g  = (const float*)d_in[18];
    const float* b_o  = (const float*)d_in[19];

    float* out   = (float*)d_out;
    float* h_out = out;
    float* c_out = out + (size_t)Bsz * Hd;

    cudaFuncSetAttribute(gemm_mma, cudaFuncAttributeMaxDynamicSharedMemorySize, SMEM_BYTES);

    const int n = Bsz * Hd;

    conv_act3<<<dim3(n/(256*4), 3), 256>>>(x, h_prev, c_prev);

    WPtrs wp = {{w_xi, w_hi, w_ci, w_xf, w_hf, w_cf, w_xg, w_hg, w_xo, w_ho, w_co, w_c, w_i}};
    conv_w<<<dim3(Kd/32, Hd/32, 13), 256>>>(wp);

    // gemm1: groups 0..4, each N=2048 -> 8 n-tiles; grid (m-tiles, group*8+ntile)
    gemm_mma<<<dim3(Bsz/BM, 5*8), THREADS, SMEM_BYTES>>>(0, b_i, b_f, b_g, b_o);

    cell_kernel<<<n/256, 256>>>(c_prev, c_out);

    // gemm2: groups 5..6
    gemm_mma<<<dim3(Bsz/BM, 2*8), THREADS, SMEM_BYTES>>>(5, nullptr, nullptr, nullptr, nullptr);

    out_kernel<<<n/256, 256>>>(h_out);
}

// round 4
// speedup vs baseline: 2.6551x; 1.2385x over previous
#include <cuda_runtime.h>
#include <cuda_bf16.h>
#include <math.h>
#include <stdint.h>

// ---------------- problem dims ----------------
#define Bsz 4096
#define Hd  2048
#define Kd  2048
#define AP  (4096ull*2048ull)   // activation plane elems
#define WP  (2048ull*2048ull)   // weight plane elems

// ---------------- device scratch ----------------
__device__ float g_Z [(size_t)Bsz*(5*Hd)];  // [B,5H]: i|f|g|o_part|resid
__device__ float g_Z2[(size_t)Bsz*(2*Hd)];  // [B,2H]: c@w_co | tanh(c)@w_c
// bf16 activations [plane][B][K]; plane = 2*act + split
// act: 0=x 1=h 2=c_prev 3=c_new 4=tanh(c_new)
__device__ __nv_bfloat16 g_Act[10ull*AP];
// bf16 weights transposed [plane][N][K]; plane = 2*widx + split
// widx: 0 wxi 1 whi 2 wci 3 wxf 4 whf 5 wcf 6 wxg 7 whg 8 wxo 9 who 10 wco 11 wc 12 wi
__device__ __nv_bfloat16 g_Wt[26ull*WP];

// ---------------- unit tables ----------------
// groups: 0=i 1=f 2=g 3=o 4=resid 5=co 6=c ; each unit = (activation, weight)
__constant__ int c_nunit[7] = {3, 3, 2, 2, 1, 1, 1};
__constant__ unsigned char c_unit_a[7][3] = {
    {0,1,2}, {0,1,2}, {0,1,0}, {0,1,0}, {0,0,0}, {3,0,0}, {4,0,0}
};
__constant__ unsigned char c_unit_w[7][3] = {
    {0,1,2}, {3,4,5}, {6,7,0}, {8,9,0}, {12,0,0}, {10,0,0}, {11,0,0}
};

// ---------------- GEMM tiling ----------------
#define BM 256
#define BN 128
#define BKc 32
#define KPAD 40                   // 32 + 8 pad for conflict-free ldmatrix
#define THREADS 512
#define A_PL (BM*KPAD)            // 10240 elems per A plane
#define W_PL (BN*KPAD)            // 5120 elems per W plane
#define ST_ELEMS (2*A_PL + 2*W_PL) // 30720 elems = 61440 B / stage
#define STAGES 3
#define SMEM_BYTES (STAGES*ST_ELEMS*2)   // 184320 B

__device__ __forceinline__ uint32_t smem_u32(const void* p) {
    uint32_t a;
    asm("{ .reg .u64 t; cvta.to.shared.u64 t, %1; cvt.u32.u64 %0, t; }" : "=r"(a) : "l"(p));
    return a;
}
__device__ __forceinline__ void cp_async16(uint32_t sdst, const void* gsrc) {
    asm volatile("cp.async.cg.shared.global [%0], [%1], 16;"
                 :: "r"(sdst), "l"(__cvta_generic_to_global(gsrc)) : "memory");
}
#define CP_COMMIT() asm volatile("cp.async.commit_group;" ::: "memory")
#define CP_WAIT1()  asm volatile("cp.async.wait_group 1;" ::: "memory")

__device__ __forceinline__ void ldsm_x4(uint32_t& r0, uint32_t& r1, uint32_t& r2, uint32_t& r3,
                                        uint32_t addr) {
    asm volatile("ldmatrix.sync.aligned.m8n8.x4.shared.b16 {%0,%1,%2,%3}, [%4];"
                 : "=r"(r0), "=r"(r1), "=r"(r2), "=r"(r3) : "r"(addr));
}
__device__ __forceinline__ void mma16816(float* d, const uint32_t* a, uint32_t b0, uint32_t b1) {
    asm volatile(
        "mma.sync.aligned.m16n8k16.row.col.f32.bf16.bf16.f32 "
        "{%0,%1,%2,%3}, {%4,%5,%6,%7}, {%8,%9}, {%0,%1,%2,%3};"
        : "+f"(d[0]), "+f"(d[1]), "+f"(d[2]), "+f"(d[3])
        : "r"(a[0]), "r"(a[1]), "r"(a[2]), "r"(a[3]), "r"(b0), "r"(b1));
}

// ---------------- fused split-bf16 GEMM (merged hi/lo, 512 threads) ----------------
__global__ void __launch_bounds__(THREADS, 1) gemm_mma(
    int group_base,
    const float* __restrict__ bi, const float* __restrict__ bf_,
    const float* __restrict__ bg, const float* __restrict__ bo)
{
    extern __shared__ __nv_bfloat16 smem[];
    const uint32_t sb = smem_u32(smem);

    const int tid  = threadIdx.x;
    const int lane = tid & 31;
    const int wid  = tid >> 5;      // 0..15
    const int wm   = wid >> 2;      // 0..3  (64-row slice)
    const int wn   = wid & 3;       // 0..3  (32-col slice)

    const int group = group_base + ((int)blockIdx.y >> 4);
    const int n0    = ((int)blockIdx.y & 15) * BN;
    const int m0    = (int)blockIdx.x * BM;

    const int nunit = c_nunit[group];
    const int nch   = nunit * (Kd / BKc);    // k32 chunks

    // ldmatrix per-lane byte offsets
    const uint32_t a_off = ((uint32_t)(wm*64 + (lane & 15)) * KPAD + ((lane >> 4) << 3)) * 2;
    const uint32_t w_off = ((uint32_t)(wn*32 + (lane & 7) + ((lane >> 4) << 3)) * KPAD
                            + (((lane >> 3) & 1) << 3)) * 2;

    float acc[4][4][4];
    #pragma unroll
    for (int mi = 0; mi < 4; ++mi)
        #pragma unroll
        for (int nj = 0; nj < 4; ++nj)
            #pragma unroll
            for (int r = 0; r < 4; ++r) acc[mi][nj][r] = 0.0f;

    // stage fill: 3072 x 16B chunks, 6 per thread
    #define ISSUE(tt, buf) do {                                                        \
        const int _t = (tt);                                                           \
        const int _u  = _t >> 6;                                                       \
        const int _kk = (_t & 63) * BKc;                                               \
        const __nv_bfloat16* _gAh = g_Act + (size_t)(2*c_unit_a[group][_u])*AP;        \
        const __nv_bfloat16* _gWh = g_Wt  + (size_t)(2*c_unit_w[group][_u])*WP;        \
        const uint32_t _sbase = sb + (uint32_t)(buf)*ST_ELEMS*2;                       \
        _Pragma("unroll")                                                              \
        for (int _i = 0; _i < 6; ++_i) {                                               \
            const int _cid = tid + _i*THREADS;                                         \
            if (_cid < 2048) {  /* A planes */                                         \
                const int _pl = _cid >> 10;          /* 0=hi 1=lo */                   \
                const int _b  = _cid & 1023;                                           \
                const int _r  = _b >> 2, _cc = _b & 3;                                 \
                cp_async16(_sbase + (uint32_t)(_pl*A_PL + _r*KPAD + _cc*8)*2,          \
                           _gAh + (size_t)_pl*AP + (size_t)(m0 + _r)*Kd + _kk + _cc*8);\
            } else {            /* W planes */                                         \
                const int _b  = _cid - 2048;                                           \
                const int _pl = _b >> 9;             /* 0=hi 1=lo */                   \
                const int _c2 = _b & 511;                                              \
                const int _r  = _c2 >> 2, _cc = _c2 & 3;                               \
                cp_async16(_sbase + (uint32_t)(2*A_PL + _pl*W_PL + _r*KPAD + _cc*8)*2, \
                           _gWh + (size_t)_pl*WP + (size_t)(n0 + _r)*Kd + _kk + _cc*8);\
            }                                                                          \
        }                                                                              \
    } while (0)

    // prologue: stages 0,1
    ISSUE(0, 0); CP_COMMIT();
    ISSUE(1, 1); CP_COMMIT();

    int buf = 0;
    for (int t = 0; t < nch; ++t) {
        CP_WAIT1();
        __syncthreads();

        if (t + 2 < nch) {
            int nb = buf + 2; if (nb >= 3) nb -= 3;
            ISSUE(t + 2, nb);
        }
        CP_COMMIT();   // always commit to keep group counts aligned

        const uint32_t st  = sb + (uint32_t)buf*ST_ELEMS*2;
        const uint32_t stw = st + (uint32_t)(2*A_PL)*2;

        #pragma unroll
        for (int ks = 0; ks < 2; ++ks) {
            const uint32_t kso = (uint32_t)(ks*16)*2;
            uint32_t ah[4][4], bh[2][4], bl[2][4];
            #pragma unroll
            for (int mi = 0; mi < 4; ++mi)
                ldsm_x4(ah[mi][0], ah[mi][1], ah[mi][2], ah[mi][3],
                        st + a_off + (uint32_t)(mi*16*KPAD)*2 + kso);
            #pragma unroll
            for (int nt = 0; nt < 2; ++nt)
                ldsm_x4(bh[nt][0], bh[nt][1], bh[nt][2], bh[nt][3],
                        stw + w_off + (uint32_t)(nt*16*KPAD)*2 + kso);
            #pragma unroll
            for (int nt = 0; nt < 2; ++nt)
                ldsm_x4(bl[nt][0], bl[nt][1], bl[nt][2], bl[nt][3],
                        stw + (uint32_t)W_PL*2 + w_off + (uint32_t)(nt*16*KPAD)*2 + kso);

            // combo 0: A_hi x W_hi
            #pragma unroll
            for (int mi = 0; mi < 4; ++mi)
                #pragma unroll
                for (int nj = 0; nj < 4; ++nj)
                    mma16816(acc[mi][nj], ah[mi],
                             bh[nj >> 1][(nj & 1)*2], bh[nj >> 1][(nj & 1)*2 + 1]);
            // combo 1: A_hi x W_lo
            #pragma unroll
            for (int mi = 0; mi < 4; ++mi)
                #pragma unroll
                for (int nj = 0; nj < 4; ++nj)
                    mma16816(acc[mi][nj], ah[mi],
                             bl[nj >> 1][(nj & 1)*2], bl[nj >> 1][(nj & 1)*2 + 1]);
            // combo 2: A_lo x W_hi
            uint32_t al[4][4];
            #pragma unroll
            for (int mi = 0; mi < 4; ++mi)
                ldsm_x4(al[mi][0], al[mi][1], al[mi][2], al[mi][3],
                        st + (uint32_t)A_PL*2 + a_off + (uint32_t)(mi*16*KPAD)*2 + kso);
            #pragma unroll
            for (int mi = 0; mi < 4; ++mi)
                #pragma unroll
                for (int nj = 0; nj < 4; ++nj)
                    mma16816(acc[mi][nj], al[mi],
                             bh[nj >> 1][(nj & 1)*2], bh[nj >> 1][(nj & 1)*2 + 1]);
        }
        if (++buf == 3) buf = 0;
    }

    // ---- epilogue ----
    float* zout; size_t ldz; int colbase;
    const float* bias = nullptr;
    if (group < 5) {
        zout = g_Z;  ldz = 5*Hd; colbase = group*Hd + n0;
        if      (group == 0) bias = bi;
        else if (group == 1) bias = bf_;
        else if (group == 2) bias = bg;
        else if (group == 3) bias = bo;
    } else {
        zout = g_Z2; ldz = 2*Hd; colbase = (group - 5)*Hd + n0;
    }

    const int gid = lane >> 2;
    const int tig = lane & 3;

    #pragma unroll
    for (int mi = 0; mi < 4; ++mi) {
        const int row = m0 + wm*64 + mi*16 + gid;
        #pragma unroll
        for (int nj = 0; nj < 4; ++nj) {
            const int ncol = wn*32 + nj*8 + tig*2;
            float b0 = 0.f, b1 = 0.f;
            if (bias) { b0 = bias[n0 + ncol]; b1 = bias[n0 + ncol + 1]; }
            float2 v0 = make_float2(acc[mi][nj][0] + b0, acc[mi][nj][1] + b1);
            float2 v1 = make_float2(acc[mi][nj][2] + b0, acc[mi][nj][3] + b1);
            *(float2*)(zout + (size_t)row       * ldz + colbase + ncol) = v0;
            *(float2*)(zout + (size_t)(row + 8) * ldz + colbase + ncol) = v1;
        }
    }
}

// ---------------- conversion kernels ----------------
__device__ __forceinline__ void split_store(__nv_bfloat16* hi, __nv_bfloat16* lo,
                                            size_t idx, float v) {
    __nv_bfloat16 h = __float2bfloat16_rn(v);
    hi[idx] = h;
    lo[idx] = __float2bfloat16_rn(v - __bfloat162float(h));
}

__global__ void __launch_bounds__(256) conv_act3(
    const float* __restrict__ x, const float* __restrict__ h, const float* __restrict__ c)
{
    const int act = blockIdx.y;
    const float* s = (act == 0) ? x : (act == 1) ? h : c;
    const size_t i = ((size_t)blockIdx.x*256 + threadIdx.x) * 4;
    float4 v = *(const float4*)(s + i);
    __nv_bfloat16* hi = g_Act + (size_t)(2*act)*AP;
    __nv_bfloat16* lo = hi + AP;
    split_store(hi, lo, i+0, v.x);
    split_store(hi, lo, i+1, v.y);
    split_store(hi, lo, i+2, v.z);
    split_store(hi, lo, i+3, v.w);
}

struct WPtrs { const float* p[13]; };

__global__ void __launch_bounds__(256) conv_w(WPtrs wp)
{
    __shared__ float t[32][33];
    const int widx = blockIdx.z;
    const float* w = wp.p[widx];
    const int tx = threadIdx.x & 31;
    const int ty = threadIdx.x >> 5;
    const int k0 = blockIdx.x * 32;
    const int n0 = blockIdx.y * 32;
    #pragma unroll
    for (int r = 0; r < 4; ++r)
        t[ty + 8*r][tx] = w[(size_t)(k0 + ty + 8*r)*Hd + n0 + tx];
    __syncthreads();
    __nv_bfloat16* hi = g_Wt + (size_t)(2*widx)*WP;
    __nv_bfloat16* lo = hi + WP;
    #pragma unroll
    for (int r = 0; r < 4; ++r) {
        const float v = t[tx][ty + 8*r];
        const size_t o = (size_t)(n0 + ty + 8*r)*Kd + k0 + tx;
        __nv_bfloat16 hb = __float2bfloat16_rn(v);
        hi[o] = hb;
        lo[o] = __float2bfloat16_rn(v - __bfloat162float(hb));
    }
}

// ---------------- elementwise kernels ----------------
__global__ void __launch_bounds__(256) cell_kernel(
    const float* __restrict__ c_prev, float* __restrict__ c_out)
{
    const int idx = blockIdx.x * 256 + threadIdx.x;
    const int m = idx >> 11;
    const int j = idx & (Hd - 1);
    const float* zr = g_Z + (size_t)m * (5*Hd);
    const float iv = zr[j];
    const float fv = zr[Hd + j];
    const float gv = zr[2*Hd + j];
    const float cp = c_prev[idx];
    const float si = 1.0f / (1.0f + expf(-iv));
    const float sf = 1.0f / (1.0f + expf(-fv));
    const float cn = sf * cp + si * tanhf(gv);
    c_out[idx] = cn;
    const float tc = tanhf(cn);
    split_store(g_Act + 6*AP, g_Act + 7*AP, idx, cn);
    split_store(g_Act + 8*AP, g_Act + 9*AP, idx, tc);
}

__global__ void __launch_bounds__(256) out_kernel(float* __restrict__ h_out)
{
    const int idx = blockIdx.x * 256 + threadIdx.x;
    const int m = idx >> 11;
    const int j = idx & (Hd - 1);
    const float* zr  = g_Z  + (size_t)m * (5*Hd);
    const float* z2r = g_Z2 + (size_t)m * (2*Hd);
    const float o = zr[3*Hd + j] + z2r[j];
    const float t = z2r[Hd + j] + zr[4*Hd + j];
    h_out[idx] = tanhf(o) * t;
}

// ---------------- host launcher ----------------
extern "C" void kernel_launch(void* const* d_in, const int* in_sizes, int n_in,
                              void* d_out, int out_size)
{
    const float* x      = (const float*)d_in[0];
    const float* h_prev = (const float*)d_in[1];
    const float* c_prev = (const float*)d_in[2];
    const float* w_xi = (const float*)d_in[3];
    const float* w_hi = (const float*)d_in[4];
    const float* w_ci = (const float*)d_in[5];
    const float* w_xf = (const float*)d_in[6];
    const float* w_hf = (const float*)d_in[7];
    const float* w_cf = (const float*)d_in[8];
    const float* w_xg = (const float*)d_in[9];
    const float* w_hg = (const float*)d_in[10];
    const float* w_xo = (const float*)d_in[11];
    const float* w_ho = (const float*)d_in[12];
    const float* w_co = (const float*)d_in[13];
    const float* w_c  = (const float*)d_in[14];
    const float* w_i  = (const float*)d_in[15];
    const float* b_i  = (const float*)d_in[16];
    const float* b_f  = (const float*)d_in[17];
    const float* b_g  = (const float*)d_in[18];
    const float* b_o  = (const float*)d_in[19];

    float* out   = (float*)d_out;
    float* h_out = out;
    float* c_out = out + (size_t)Bsz * Hd;

    cudaFuncSetAttribute(gemm_mma, cudaFuncAttributeMaxDynamicSharedMemorySize, SMEM_BYTES);

    const int n = Bsz * Hd;

    conv_act3<<<dim3(n/(256*4), 3), 256>>>(x, h_prev, c_prev);

    WPtrs wp = {{w_xi, w_hi, w_ci, w_xf, w_hf, w_cf, w_xg, w_hg, w_xo, w_ho, w_co, w_c, w_i}};
    conv_w<<<dim3(Kd/32, Hd/32, 13), 256>>>(wp);

    // gemm1: groups 0..4; 16 n-tiles per group, 16 m-tiles
    gemm_mma<<<dim3(Bsz/BM, 5*16), THREADS, SMEM_BYTES>>>(0, b_i, b_f, b_g, b_o);

    cell_kernel<<<n/256, 256>>>(c_prev, c_out);

    // gemm2: groups 5..6
    gemm_mma<<<dim3(Bsz/BM, 2*16), THREADS, SMEM_BYTES>>>(5, nullptr, nullptr, nullptr, nullptr);

    out_kernel<<<n/256, 256>>>(h_out);
}

// round 5
// speedup vs baseline: 3.9128x; 1.4737x over previous
#include <cuda_runtime.h>
#include <cuda_fp16.h>
#include <math.h>
#include <stdint.h>

// ---------------- problem dims ----------------
#define Bsz 4096
#define Hd  2048
#define Kd  2048
#define AP  (4096ull*2048ull)   // activation plane elems
#define WP  (2048ull*2048ull)   // weight plane elems

// ---------------- device scratch ----------------
__device__ float g_Z [(size_t)Bsz*(5*Hd)];  // [B,5H]: i|f|g|o_part|resid
__device__ float g_Z2[(size_t)Bsz*(2*Hd)];  // [B,2H]: c@w_co | tanh(c)@w_c
// fp16 activations [plane][B][K]; plane: 0=x 1=h 2=c_prev 3=c_new 4=tanh(c_new)
__device__ __half g_Act[5ull*AP];
// fp16 weights transposed [plane][N][K]; plane = 2*widx + (0=hi,1=lo)
// widx: 0 wxi 1 whi 2 wci 3 wxf 4 whf 5 wcf 6 wxg 7 whg 8 wxo 9 who 10 wco 11 wc 12 wi
__device__ __half g_Wt[26ull*WP];

// ---------------- unit tables ----------------
// groups: 0=i 1=f 2=g 3=o 4=resid 5=co 6=c ; each unit = (activation, weight)
__constant__ int c_nunit[7] = {3, 3, 2, 2, 1, 1, 1};
__constant__ unsigned char c_unit_a[7][3] = {
    {0,1,2}, {0,1,2}, {0,1,0}, {0,1,0}, {0,0,0}, {3,0,0}, {4,0,0}
};
__constant__ unsigned char c_unit_w[7][3] = {
    {0,1,2}, {3,4,5}, {6,7,0}, {8,9,0}, {12,0,0}, {10,0,0}, {11,0,0}
};

// ---------------- GEMM tiling ----------------
#define BM 128
#define BN 128
#define BKc 32
#define KPAD 40                    // 32 data + 8 pad: conflict-free ldmatrix
#define THREADS 256
#define A_PL (BM*KPAD)             // 5120 elems (one fp16 A plane)
#define W_PL (BN*KPAD)             // 5120 elems per W plane (hi, lo)
#define ST_ELEMS (A_PL + 2*W_PL)   // 15360 elems = 30720 B / stage
#define STAGES 3
#define SMEM_BYTES (STAGES*ST_ELEMS*2)   // 92160 B -> 2 CTAs/SM

__device__ __forceinline__ uint32_t smem_u32(const void* p) {
    uint32_t a;
    asm("{ .reg .u64 t; cvta.to.shared.u64 t, %1; cvt.u32.u64 %0, t; }" : "=r"(a) : "l"(p));
    return a;
}
__device__ __forceinline__ void cp_async16(uint32_t sdst, const void* gsrc) {
    asm volatile("cp.async.cg.shared.global [%0], [%1], 16;"
                 :: "r"(sdst), "l"(__cvta_generic_to_global(gsrc)) : "memory");
}
#define CP_COMMIT() asm volatile("cp.async.commit_group;" ::: "memory")
#define CP_WAIT1()  asm volatile("cp.async.wait_group 1;" ::: "memory")

__device__ __forceinline__ void ldsm_x4(uint32_t& r0, uint32_t& r1, uint32_t& r2, uint32_t& r3,
                                        uint32_t addr) {
    asm volatile("ldmatrix.sync.aligned.m8n8.x4.shared.b16 {%0,%1,%2,%3}, [%4];"
                 : "=r"(r0), "=r"(r1), "=r"(r2), "=r"(r3) : "r"(addr));
}
__device__ __forceinline__ void mma16816(float* d, const uint32_t* a, uint32_t b0, uint32_t b1) {
    asm volatile(
        "mma.sync.aligned.m16n8k16.row.col.f32.f16.f16.f32 "
        "{%0,%1,%2,%3}, {%4,%5,%6,%7}, {%8,%9}, {%0,%1,%2,%3};"
        : "+f"(d[0]), "+f"(d[1]), "+f"(d[2]), "+f"(d[3])
        : "r"(a[0]), "r"(a[1]), "r"(a[2]), "r"(a[3]), "r"(b0), "r"(b1));
}

// ---------------- 2-pass fp16 GEMM (A single, W hi/lo merged per stage) ----------------
__global__ void __launch_bounds__(THREADS, 2) gemm_mma(
    int group_base,
    const float* __restrict__ bi, const float* __restrict__ bf_,
    const float* __restrict__ bg, const float* __restrict__ bo)
{
    extern __shared__ __half smem[];
    const uint32_t sb = smem_u32(smem);

    const int tid  = threadIdx.x;
    const int lane = tid & 31;
    const int wid  = tid >> 5;      // 0..7
    const int wm   = wid >> 2;      // 0..1  (64-row slice)
    const int wn   = wid & 3;       // 0..3  (32-col slice)

    const int group = group_base + ((int)blockIdx.y >> 4);
    const int n0    = ((int)blockIdx.y & 15) * BN;
    const int m0    = (int)blockIdx.x * BM;

    const int nunit = c_nunit[group];
    const int nch   = nunit * (Kd / BKc);    // k32 chunks

    // ldmatrix per-lane byte offsets
    const uint32_t a_off = ((uint32_t)(wm*64 + (lane & 15)) * KPAD + ((lane >> 4) << 3)) * 2;
    const uint32_t w_off = ((uint32_t)(wn*32 + (lane & 7) + ((lane >> 4) << 3)) * KPAD
                            + (((lane >> 3) & 1) << 3)) * 2;

    float acc[4][4][4];
    #pragma unroll
    for (int mi = 0; mi < 4; ++mi)
        #pragma unroll
        for (int nj = 0; nj < 4; ++nj)
            #pragma unroll
            for (int r = 0; r < 4; ++r) acc[mi][nj][r] = 0.0f;

    // stage fill: 1536 x 16B chunks, 6 per thread
    // [0,512): A plane; [512,1024): W hi; [1024,1536): W lo
    #define ISSUE(tt, buf) do {                                                        \
        const int _t = (tt);                                                           \
        const int _u  = _t >> 6;                                                       \
        const int _kk = (_t & 63) * BKc;                                               \
        const __half* _gA = g_Act + (size_t)c_unit_a[group][_u]*AP;                    \
        const __half* _gW = g_Wt  + (size_t)(2*c_unit_w[group][_u])*WP;                \
        const uint32_t _sbase = sb + (uint32_t)(buf)*ST_ELEMS*2;                       \
        _Pragma("unroll")                                                              \
        for (int _i = 0; _i < 6; ++_i) {                                               \
            const int _cid = tid + _i*THREADS;                                         \
            if (_cid < 512) {                                                          \
                const int _r = _cid >> 2, _cc = _cid & 3;                              \
                cp_async16(_sbase + (uint32_t)(_r*KPAD + _cc*8)*2,                     \
                           _gA + (size_t)(m0 + _r)*Kd + _kk + _cc*8);                  \
            } else {                                                                   \
                const int _b  = _cid - 512;                                            \
                const int _pl = _b >> 9;             /* 0=hi 1=lo */                   \
                const int _c2 = _b & 511;                                              \
                const int _r  = _c2 >> 2, _cc = _c2 & 3;                               \
                cp_async16(_sbase + (uint32_t)(A_PL + _pl*W_PL + _r*KPAD + _cc*8)*2,   \
                           _gW + (size_t)_pl*WP + (size_t)(n0 + _r)*Kd + _kk + _cc*8); \
            }                                                                          \
        }                                                                              \
    } while (0)

    // prologue: stages 0,1
    ISSUE(0, 0); CP_COMMIT();
    ISSUE(1, 1); CP_COMMIT();

    int buf = 0;
    for (int t = 0; t < nch; ++t) {
        CP_WAIT1();
        __syncthreads();

        if (t + 2 < nch) {
            int nb = buf + 2; if (nb >= 3) nb -= 3;
            ISSUE(t + 2, nb);
        }
        CP_COMMIT();   // always commit to keep group counts aligned

        const uint32_t st  = sb + (uint32_t)buf*ST_ELEMS*2;
        const uint32_t stw = st + (uint32_t)A_PL*2;

        #pragma unroll
        for (int ks = 0; ks < 2; ++ks) {
            const uint32_t kso = (uint32_t)(ks*16)*2;
            uint32_t a[4][4], bh[2][4], bl[2][4];
            #pragma unroll
            for (int mi = 0; mi < 4; ++mi)
                ldsm_x4(a[mi][0], a[mi][1], a[mi][2], a[mi][3],
                        st + a_off + (uint32_t)(mi*16*KPAD)*2 + kso);
            #pragma unroll
            for (int nt = 0; nt < 2; ++nt)
                ldsm_x4(bh[nt][0], bh[nt][1], bh[nt][2], bh[nt][3],
                        stw + w_off + (uint32_t)(nt*16*KPAD)*2 + kso);
            #pragma unroll
            for (int nt = 0; nt < 2; ++nt)
                ldsm_x4(bl[nt][0], bl[nt][1], bl[nt][2], bl[nt][3],
                        stw + (uint32_t)W_PL*2 + w_off + (uint32_t)(nt*16*KPAD)*2 + kso);

            // pass 0: A x W_hi
            #pragma unroll
            for (int mi = 0; mi < 4; ++mi)
                #pragma unroll
                for (int nj = 0; nj < 4; ++nj)
                    mma16816(acc[mi][nj], a[mi],
                             bh[nj >> 1][(nj & 1)*2], bh[nj >> 1][(nj & 1)*2 + 1]);
            // pass 1: A x W_lo
            #pragma unroll
            for (int mi = 0; mi < 4; ++mi)
                #pragma unroll
                for (int nj = 0; nj < 4; ++nj)
                    mma16816(acc[mi][nj], a[mi],
                             bl[nj >> 1][(nj & 1)*2], bl[nj >> 1][(nj & 1)*2 + 1]);
        }
        if (++buf == 3) buf = 0;
    }

    // ---- epilogue ----
    float* zout; size_t ldz; int colbase;
    const float* bias = nullptr;
    if (group < 5) {
        zout = g_Z;  ldz = 5*Hd; colbase = group*Hd + n0;
        if      (group == 0) bias = bi;
        else if (group == 1) bias = bf_;
        else if (group == 2) bias = bg;
        else if (group == 3) bias = bo;
    } else {
        zout = g_Z2; ldz = 2*Hd; colbase = (group - 5)*Hd + n0;
    }

    const int gid = lane >> 2;
    const int tig = lane & 3;

    #pragma unroll
    for (int mi = 0; mi < 4; ++mi) {
        const int row = m0 + wm*64 + mi*16 + gid;
        #pragma unroll
        for (int nj = 0; nj < 4; ++nj) {
            const int ncol = wn*32 + nj*8 + tig*2;
            float b0 = 0.f, b1 = 0.f;
            if (bias) { b0 = bias[n0 + ncol]; b1 = bias[n0 + ncol + 1]; }
            float2 v0 = make_float2(acc[mi][nj][0] + b0, acc[mi][nj][1] + b1);
            float2 v1 = make_float2(acc[mi][nj][2] + b0, acc[mi][nj][3] + b1);
            *(float2*)(zout + (size_t)row       * ldz + colbase + ncol) = v0;
            *(float2*)(zout + (size_t)(row + 8) * ldz + colbase + ncol) = v1;
        }
    }
}

// ---------------- conversion kernels ----------------
// x/h/c fp32 -> fp16 planes 0..2
__global__ void __launch_bounds__(256) conv_act3(
    const float* __restrict__ x, const float* __restrict__ h, const float* __restrict__ c)
{
    const int act = blockIdx.y;
    const float* s = (act == 0) ? x : (act == 1) ? h : c;
    const size_t i = ((size_t)blockIdx.x*256 + threadIdx.x) * 4;
    float4 v = *(const float4*)(s + i);
    __half* dst = g_Act + (size_t)act*AP;
    dst[i+0] = __float2half_rn(v.x);
    dst[i+1] = __float2half_rn(v.y);
    dst[i+2] = __float2half_rn(v.z);
    dst[i+3] = __float2half_rn(v.w);
}

struct WPtrs { const float* p[13]; };

// W[K][N] fp32 -> g_Wt[N][K] fp16 hi/lo (transpose via smem tile)
__global__ void __launch_bounds__(256) conv_w(WPtrs wp)
{
    __shared__ float t[32][33];
    const int widx = blockIdx.z;
    const float* w = wp.p[widx];
    const int tx = threadIdx.x & 31;
    const int ty = threadIdx.x >> 5;
    const int k0 = blockIdx.x * 32;
    const int n0 = blockIdx.y * 32;
    #pragma unroll
    for (int r = 0; r < 4; ++r)
        t[ty + 8*r][tx] = w[(size_t)(k0 + ty + 8*r)*Hd + n0 + tx];
    __syncthreads();
    __half* hi = g_Wt + (size_t)(2*widx)*WP;
    __half* lo = hi + WP;
    #pragma unroll
    for (int r = 0; r < 4; ++r) {
        const float v = t[tx][ty + 8*r];
        const size_t o = (size_t)(n0 + ty + 8*r)*Kd + k0 + tx;
        __half hb = __float2half_rn(v);
        hi[o] = hb;
        lo[o] = __float2half_rn(v - __half2float(hb));
    }
}

// ---------------- elementwise kernels ----------------
__global__ void __launch_bounds__(256) cell_kernel(
    const float* __restrict__ c_prev, float* __restrict__ c_out)
{
    const int idx = blockIdx.x * 256 + threadIdx.x;
    const int m = idx >> 11;
    const int j = idx & (Hd - 1);
    const float* zr = g_Z + (size_t)m * (5*Hd);
    const float iv = zr[j];
    const float fv = zr[Hd + j];
    const float gv = zr[2*Hd + j];
    const float cp = c_prev[idx];
    const float si = 1.0f / (1.0f + expf(-iv));
    const float sf = 1.0f / (1.0f + expf(-fv));
    const float cn = sf * cp + si * tanhf(gv);
    c_out[idx] = cn;
    const float tc = tanhf(cn);
    g_Act[3*AP + idx] = __float2half_rn(cn);
    g_Act[4*AP + idx] = __float2half_rn(tc);
}

__global__ void __launch_bounds__(256) out_kernel(float* __restrict__ h_out)
{
    const int idx = blockIdx.x * 256 + threadIdx.x;
    const int m = idx >> 11;
    const int j = idx & (Hd - 1);
    const float* zr  = g_Z  + (size_t)m * (5*Hd);
    const float* z2r = g_Z2 + (size_t)m * (2*Hd);
    const float o = zr[3*Hd + j] + z2r[j];
    const float t = z2r[Hd + j] + zr[4*Hd + j];
    h_out[idx] = tanhf(o) * t;
}

// ---------------- host launcher ----------------
extern "C" void kernel_launch(void* const* d_in, const int* in_sizes, int n_in,
                              void* d_out, int out_size)
{
    const float* x      = (const float*)d_in[0];
    const float* h_prev = (const float*)d_in[1];
    const float* c_prev = (const float*)d_in[2];
    const float* w_xi = (const float*)d_in[3];
    const float* w_hi = (const float*)d_in[4];
    const float* w_ci = (const float*)d_in[5];
    const float* w_xf = (const float*)d_in[6];
    const float* w_hf = (const float*)d_in[7];
    const float* w_cf = (const float*)d_in[8];
    const float* w_xg = (const float*)d_in[9];
    const float* w_hg = (const float*)d_in[10];
    const float* w_xo = (const float*)d_in[11];
    const float* w_ho = (const float*)d_in[12];
    const float* w_co = (const float*)d_in[13];
    const float* w_c  = (const float*)d_in[14];
    const float* w_i  = (const float*)d_in[15];
    const float* b_i  = (const float*)d_in[16];
    const float* b_f  = (const float*)d_in[17];
    const float* b_g  = (const float*)d_in[18];
    const float* b_o  = (const float*)d_in[19];

    float* out   = (float*)d_out;
    float* h_out = out;
    float* c_out = out + (size_t)Bsz * Hd;

    cudaFuncSetAttribute(gemm_mma, cudaFuncAttributeMaxDynamicSharedMemorySize, SMEM_BYTES);

    const int n = Bsz * Hd;

    conv_act3<<<dim3(n/(256*4), 3), 256>>>(x, h_prev, c_prev);

    WPtrs wp = {{w_xi, w_hi, w_ci, w_xf, w_hf, w_cf, w_xg, w_hg, w_xo, w_ho, w_co, w_c, w_i}};
    conv_w<<<dim3(Kd/32, Hd/32, 13), 256>>>(wp);

    // gemm1: groups 0..4; 16 n-tiles per group, 32 m-tiles
    gemm_mma<<<dim3(Bsz/BM, 5*16), THREADS, SMEM_BYTES>>>(0, b_i, b_f, b_g, b_o);

    cell_kernel<<<n/256, 256>>>(c_prev, c_out);

    // gemm2: groups 5..6
    gemm_mma<<<dim3(Bsz/BM, 2*16), THREADS, SMEM_BYTES>>>(5, nullptr, nullptr, nullptr, nullptr);

    out_kernel<<<n/256, 256>>>(h_out);
}